// round 2
// baseline (speedup 1.0000x reference)
#include <cuda_runtime.h>
#include <math.h>
#include <stdint.h>

// Problem constants
#define DDIM 1024
#define TDIM 2048
#define BDIM 32
#define MTOT 65536          // B*T
#define W2OFF DDIM          // W2 = W[:, D:2D]
#define WSTRIDE (2 * DDIM)

// GEMM tiling
#define BM 128
#define BN 128
#define BK 16
#define SST 20              // smem row stride (floats): 80B = 16B-aligned, (20r+c)%32 permutation -> conflict-free
#define NTILES (DDIM / BN)  // 8
#define KT (DDIM / BK)      // 64

// Scratch (static __device__ arrays: allocation-free)
__device__ float g_qh[BDIM * DDIM];
__device__ float g_part[(size_t)NTILES * MTOT];

// ---------------------------------------------------------------------------
__device__ __forceinline__ uint32_t f2tf32(float x) {
    uint32_t r;
    asm("cvt.rna.tf32.f32 %0, %1;" : "=r"(r) : "f"(x));
    return r;
}

__device__ __forceinline__ void mma_tf32(float* d, const uint32_t* a, const uint32_t* b) {
    asm volatile(
        "mma.sync.aligned.m16n8k8.row.col.f32.tf32.tf32.f32 "
        "{%0,%1,%2,%3}, {%4,%5,%6,%7}, {%8,%9}, {%0,%1,%2,%3};"
        : "+f"(d[0]), "+f"(d[1]), "+f"(d[2]), "+f"(d[3])
        : "r"(a[0]), "r"(a[1]), "r"(a[2]), "r"(a[3]), "r"(b[0]), "r"(b[1]));
}

__device__ __forceinline__ void cp16(uint32_t dst, const float* src) {
    asm volatile("cp.async.cg.shared.global [%0], [%1], 16;" :: "r"(dst), "l"(src));
}

// ---------------------------------------------------------------------------
// Kernel 1: qh[b,d] = W1[d,:] . hidden[b,:] + bias[d]   (warp per output)
__global__ __launch_bounds__(256) void qh_kernel(
    const float* __restrict__ hidden, const float* __restrict__ W,
    const float* __restrict__ bias)
{
    const int b = blockIdx.y;
    const int warp = threadIdx.x >> 5;
    const int lane = threadIdx.x & 31;
    const int d = blockIdx.x * 8 + warp;

    const float* wr = W + (size_t)d * WSTRIDE;   // W1 row d
    const float* h  = hidden + (size_t)b * DDIM;

    float acc = 0.f;
    #pragma unroll 8
    for (int k = lane; k < DDIM; k += 32) acc += wr[k] * h[k];
    #pragma unroll
    for (int o = 16; o > 0; o >>= 1) acc += __shfl_xor_sync(0xFFFFFFFFu, acc, o);
    if (lane == 0) g_qh[(size_t)b * DDIM + d] = acc + bias[d];
}

// ---------------------------------------------------------------------------
// Kernel 2: fused GEMM + relu + dot(v) partial reduction.
//   A = enc [MTOT, D] row-major; Bmat = W2 [N=D, K=D] row-major (k contiguous)
//   Writes g_part[nx][m] = sum over this CTA's 128 d-columns of v[d]*relu(acc+qh).
__global__ __launch_bounds__(256) void fused_gemm(
    const float* __restrict__ A, const float* __restrict__ W,
    const float* __restrict__ v)
{
    __shared__ float As[2][BM * SST];
    __shared__ float Bs[2][BN * SST];
    __shared__ float partial[4][BM];

    const int tid  = threadIdx.x;
    const int lane = tid & 31;
    const int warp = tid >> 5;
    const int wm   = warp >> 2;     // 0..1  (M direction, 64 rows each)
    const int wn   = warp & 3;      // 0..3  (N direction, 32 cols each)
    const int gid  = lane >> 2;
    const int tig  = lane & 3;

    const int nx   = blockIdx.x;
    const int m0   = blockIdx.y * BM;
    const int n0   = nx * BN;
    const int bidx = m0 >> 11;      // 2048 rows per batch; BM=128 divides evenly

    float acc[4][4][4];
    #pragma unroll
    for (int i = 0; i < 4; i++)
        #pragma unroll
        for (int j = 0; j < 4; j++)
            #pragma unroll
            for (int k = 0; k < 4; k++) acc[i][j][k] = 0.f;

    const float* Ag = A + (size_t)m0 * DDIM;
    const float* Bg = W + (size_t)n0 * WSTRIDE + W2OFF;

    // cp.async mapping: 512 16B-chunks per matrix per tile; thread does chunks {tid, tid+256}
    const int r0c = tid >> 2;            // 0..63
    const int cc  = tid & 3;             // 0..3 (chunk within 16-float row)
    const int r1c = r0c + 64;

    #define ISSUE_TILE(ktile, buf)                                                        \
    do {                                                                                  \
        const int k0_ = (ktile) * BK;                                                     \
        cp16((uint32_t)__cvta_generic_to_shared(&As[(buf)][r0c * SST + cc * 4]),          \
             Ag + (size_t)r0c * DDIM + k0_ + cc * 4);                                     \
        cp16((uint32_t)__cvta_generic_to_shared(&As[(buf)][r1c * SST + cc * 4]),          \
             Ag + (size_t)r1c * DDIM + k0_ + cc * 4);                                     \
        cp16((uint32_t)__cvta_generic_to_shared(&Bs[(buf)][r0c * SST + cc * 4]),          \
             Bg + (size_t)r0c * WSTRIDE + k0_ + cc * 4);                                  \
        cp16((uint32_t)__cvta_generic_to_shared(&Bs[(buf)][r1c * SST + cc * 4]),          \
             Bg + (size_t)r1c * WSTRIDE + k0_ + cc * 4);                                  \
    } while (0)

    ISSUE_TILE(0, 0);
    asm volatile("cp.async.commit_group;");

    for (int kt = 0; kt < KT; kt++) {
        const int buf = kt & 1;
        if (kt + 1 < KT) ISSUE_TILE(kt + 1, buf ^ 1);
        asm volatile("cp.async.commit_group;");
        asm volatile("cp.async.wait_group 1;");
        __syncthreads();

        #pragma unroll
        for (int ks = 0; ks < 2; ks++) {
            const int kk = ks * 8;
            uint32_t af[4][4];
            #pragma unroll
            for (int mi = 0; mi < 4; mi++) {
                const int r = wm * 64 + mi * 16 + gid;
                af[mi][0] = f2tf32(As[buf][r * SST + kk + tig]);
                af[mi][1] = f2tf32(As[buf][(r + 8) * SST + kk + tig]);
                af[mi][2] = f2tf32(As[buf][r * SST + kk + 4 + tig]);
                af[mi][3] = f2tf32(As[buf][(r + 8) * SST + kk + 4 + tig]);
            }
            uint32_t bfr[4][2];
            #pragma unroll
            for (int ni = 0; ni < 4; ni++) {
                const int c = wn * 32 + ni * 8 + gid;
                bfr[ni][0] = f2tf32(Bs[buf][c * SST + kk + tig]);
                bfr[ni][1] = f2tf32(Bs[buf][c * SST + kk + 4 + tig]);
            }
            #pragma unroll
            for (int mi = 0; mi < 4; mi++)
                #pragma unroll
                for (int ni = 0; ni < 4; ni++)
                    mma_tf32(acc[mi][ni], af[mi], bfr[ni]);
        }
        __syncthreads();
    }

    // Epilogue: relu(acc + qh) * v, reduce over this CTA's 128 d-columns.
    float pr[4][2];
    #pragma unroll
    for (int mi = 0; mi < 4; mi++) { pr[mi][0] = 0.f; pr[mi][1] = 0.f; }

    #pragma unroll
    for (int ni = 0; ni < 4; ni++) {
        const int c = n0 + wn * 32 + ni * 8 + tig * 2;
        const float q0 = g_qh[(size_t)bidx * DDIM + c];
        const float q1 = g_qh[(size_t)bidx * DDIM + c + 1];
        const float v0 = v[c];
        const float v1 = v[c + 1];
        #pragma unroll
        for (int mi = 0; mi < 4; mi++) {
            pr[mi][0] += fmaxf(acc[mi][ni][0] + q0, 0.f) * v0;
            pr[mi][0] += fmaxf(acc[mi][ni][1] + q1, 0.f) * v1;
            pr[mi][1] += fmaxf(acc[mi][ni][2] + q0, 0.f) * v0;
            pr[mi][1] += fmaxf(acc[mi][ni][3] + q1, 0.f) * v1;
        }
    }

    // reduce across the 4 lanes that hold the same rows (tig group), no atomics
    #pragma unroll
    for (int mi = 0; mi < 4; mi++)
        #pragma unroll
        for (int j = 0; j < 2; j++) {
            float p = pr[mi][j];
            p += __shfl_xor_sync(0xFFFFFFFFu, p, 1);
            p += __shfl_xor_sync(0xFFFFFFFFu, p, 2);
            if (tig == 0) partial[wn][wm * 64 + mi * 16 + j * 8 + gid] = p;
        }
    __syncthreads();

    if (tid < BM) {
        const float s = partial[0][tid] + partial[1][tid] + partial[2][tid] + partial[3][tid];
        g_part[(size_t)nx * MTOT + m0 + tid] = s;
    }
}

// ---------------------------------------------------------------------------
// Kernel 3: sum the 8 N-tile partials -> scores, softmax over T, write out.
__global__ __launch_bounds__(256) void softmax_kernel(float* __restrict__ out)
{
    const int b = blockIdx.x;
    const int tid = threadIdx.x;
    __shared__ float red[256];

    float vals[8];
    float mx = -1e30f;
    #pragma unroll
    for (int j = 0; j < 8; j++) {
        const int t = tid + j * 256;
        float s = 0.f;
        #pragma unroll
        for (int nx = 0; nx < NTILES; nx++)
            s += g_part[(size_t)nx * MTOT + (size_t)b * TDIM + t];
        vals[j] = s;
        mx = fmaxf(mx, s);
    }

    red[tid] = mx;
    __syncthreads();
    #pragma unroll
    for (int o = 128; o > 0; o >>= 1) {
        if (tid < o) red[tid] = fmaxf(red[tid], red[tid + o]);
        __syncthreads();
    }
    const float m = red[0];
    __syncthreads();

    float sum = 0.f;
    #pragma unroll
    for (int j = 0; j < 8; j++) {
        vals[j] = expf(vals[j] - m);
        sum += vals[j];
    }
    red[tid] = sum;
    __syncthreads();
    #pragma unroll
    for (int o = 128; o > 0; o >>= 1) {
        if (tid < o) red[tid] += red[tid + o];
        __syncthreads();
    }
    const float inv = 1.f / red[0];

    #pragma unroll
    for (int j = 0; j < 8; j++)
        out[(size_t)b * TDIM + tid + j * 256] = vals[j] * inv;
}

// ---------------------------------------------------------------------------
extern "C" void kernel_launch(void* const* d_in, const int* in_sizes, int n_in,
                              void* d_out, int out_size)
{
    const float* hidden = (const float*)d_in[0];
    const float* enc    = (const float*)d_in[1];
    const float* W      = (const float*)d_in[2];
    const float* bias   = (const float*)d_in[3];
    const float* v      = (const float*)d_in[4];
    float* out = (float*)d_out;

    qh_kernel<<<dim3(DDIM / 8, BDIM), 256>>>(hidden, W, bias);
    fused_gemm<<<dim3(NTILES, MTOT / BM), 256>>>(enc, W, v);
    softmax_kernel<<<BDIM, 256>>>(out);
}

// round 4
// speedup vs baseline: 1.6692x; 1.6692x over previous
#include <cuda_runtime.h>
#include <cuda_bf16.h>
#include <math.h>
#include <stdint.h>

// Problem constants
#define DDIM 1024
#define TDIM 2048
#define BDIM 32
#define MTOT 65536
#define WSTRIDE 2048        // W row stride in floats (2*D)

// GEMM tiling (bf16)
#define BM 128
#define BN 128
#define BK 32               // bf16 k-elements per stage (64B data per row)
#define SST 40              // smem row stride in bf16 (80B): (20g+t)%32 permutation -> conflict-free
#define NTILES 8            // 1024 / BN
#define KT 32               // 1024 / BK

// Scratch (static __device__ arrays: allocation-free)
__device__ __nv_bfloat16 g_encb[(size_t)MTOT * DDIM];   // enc converted to bf16
__device__ __nv_bfloat16 g_w2b[(size_t)DDIM * DDIM];    // W2 converted to bf16 [n][k]
__device__ float g_qh[BDIM * DDIM];
__device__ float g_part[(size_t)NTILES * MTOT];

// ---------------------------------------------------------------------------
__device__ __forceinline__ void mma_bf16(float* d, const uint32_t* a, const uint32_t* b) {
    asm volatile(
        "mma.sync.aligned.m16n8k16.row.col.f32.bf16.bf16.f32 "
        "{%0,%1,%2,%3}, {%4,%5,%6,%7}, {%8,%9}, {%0,%1,%2,%3};"
        : "+f"(d[0]), "+f"(d[1]), "+f"(d[2]), "+f"(d[3])
        : "r"(a[0]), "r"(a[1]), "r"(a[2]), "r"(a[3]), "r"(b[0]), "r"(b[1]));
}
__device__ __forceinline__ void cp16(uint32_t dst, const void* src) {
    asm volatile("cp.async.cg.shared.global [%0], [%1], 16;" :: "r"(dst), "l"(src));
}

// ---------------------------------------------------------------------------
// Convert enc (f32) -> g_encb (bf16). One float4 per thread.
__global__ __launch_bounds__(256) void conv_enc(const float4* __restrict__ src)
{
    const size_t i = (size_t)blockIdx.x * 256 + threadIdx.x;   // 16Mi float4s
    const float4 x = src[i];
    __nv_bfloat162 p0 = __floats2bfloat162_rn(x.x, x.y);
    __nv_bfloat162 p1 = __floats2bfloat162_rn(x.z, x.w);
    uint2 o;
    o.x = *(uint32_t*)&p0;
    o.y = *(uint32_t*)&p1;
    ((uint2*)g_encb)[i] = o;
}

// Convert W2 = W[:, 1024:2048] -> g_w2b (bf16). Block per n-row.
__global__ __launch_bounds__(256) void conv_w2(const float* __restrict__ W)
{
    const int n = blockIdx.x;
    const int t = threadIdx.x;
    const float4 x = *(const float4*)(W + (size_t)n * WSTRIDE + DDIM + t * 4);
    __nv_bfloat162 p0 = __floats2bfloat162_rn(x.x, x.y);
    __nv_bfloat162 p1 = __floats2bfloat162_rn(x.z, x.w);
    uint2 o;
    o.x = *(uint32_t*)&p0;
    o.y = *(uint32_t*)&p1;
    ((uint2*)(g_w2b + (size_t)n * DDIM))[t] = o;
}

// ---------------------------------------------------------------------------
// Kernel: qh[b,d] = W1[d,:] . hidden[b,:] + bias[d]
__global__ __launch_bounds__(256) void qh_kernel(
    const float* __restrict__ hidden, const float* __restrict__ W,
    const float* __restrict__ bias)
{
    const int b = blockIdx.y;
    const int warp = threadIdx.x >> 5;
    const int lane = threadIdx.x & 31;
    const int d = blockIdx.x * 8 + warp;

    const float* wr = W + (size_t)d * WSTRIDE;
    const float* h  = hidden + (size_t)b * DDIM;

    float acc = 0.f;
    #pragma unroll 8
    for (int k = lane; k < DDIM; k += 32) acc += wr[k] * h[k];
    #pragma unroll
    for (int o = 16; o > 0; o >>= 1) acc += __shfl_xor_sync(0xFFFFFFFFu, acc, o);
    if (lane == 0) g_qh[(size_t)b * DDIM + d] = acc + bias[d];
}

// ---------------------------------------------------------------------------
// bf16 GEMM (m16n8k16 mma.sync) + fused relu/dot(v) epilogue.
//   A = g_encb [MTOT, D]; B = g_w2b [N=D, K=D] (k contiguous -> col-major B)
__global__ __launch_bounds__(256, 2) void bf_gemm(const float* __restrict__ v)
{
    __shared__ __nv_bfloat16 As[2][BM * SST];
    __shared__ __nv_bfloat16 Bs[2][BM * SST];
    __shared__ float partial[4][BM];

    const int tid  = threadIdx.x;
    const int lane = tid & 31;
    const int warp = tid >> 5;
    const int wm   = warp >> 2;     // 0..1  (M, 64 rows each)
    const int wn   = warp & 3;      // 0..3  (N, 32 cols each)
    const int gid  = lane >> 2;     // 0..7
    const int tig  = lane & 3;      // 0..3

    const int nx   = blockIdx.x;
    const int m0   = blockIdx.y * BM;
    const int n0   = nx * BN;
    const int bidx = m0 >> 11;      // 2048 rows per batch

    float acc[4][4][4];
    #pragma unroll
    for (int i = 0; i < 4; i++)
        #pragma unroll
        for (int j = 0; j < 4; j++)
            #pragma unroll
            for (int k = 0; k < 4; k++) acc[i][j][k] = 0.f;

    // cp.async mapping: per stage per matrix = 128 rows x 4 16B-chunks = 512 ops,
    // 256 threads -> rows {r0, r0+64}, chunk cc.
    const int r0 = tid >> 2;            // 0..63
    const int cc = tid & 3;             // 0..3

    const uint32_t uA = (uint32_t)__cvta_generic_to_shared(&As[0][r0 * SST + cc * 8]);
    const uint32_t uB = (uint32_t)__cvta_generic_to_shared(&Bs[0][r0 * SST + cc * 8]);
    const uint32_t BUFB = BM * SST * 2;          // bytes per stage buffer
    const uint32_t ROWB = 64 * SST * 2;          // +64 rows in smem

    const __nv_bfloat16* pA = g_encb + (size_t)(m0 + r0) * DDIM + cc * 8;
    const __nv_bfloat16* pB = g_w2b  + (size_t)(n0 + r0) * DDIM + cc * 8;

    #define ISSUE_TILE(c, buf)                                                  \
    do {                                                                        \
        const uint32_t _bo = (uint32_t)(buf) * BUFB;                            \
        const __nv_bfloat16* _ga = pA + (size_t)(c) * BK;                       \
        const __nv_bfloat16* _gb = pB + (size_t)(c) * BK;                       \
        cp16(uA + _bo,        _ga);                                             \
        cp16(uA + _bo + ROWB, _ga + (size_t)64 * DDIM);                         \
        cp16(uB + _bo,        _gb);                                             \
        cp16(uB + _bo + ROWB, _gb + (size_t)64 * DDIM);                         \
    } while (0)

    ISSUE_TILE(0, 0);
    asm volatile("cp.async.commit_group;");

    for (int kt = 0; kt < KT; kt++) {
        const int buf = kt & 1;
        if (kt + 1 < KT) ISSUE_TILE(kt + 1, buf ^ 1);
        asm volatile("cp.async.commit_group;");
        if (kt < KT - 1) asm volatile("cp.async.wait_group 1;");
        else             asm volatile("cp.async.wait_group 0;");
        __syncthreads();

        #pragma unroll
        for (int ks = 0; ks < 2; ks++) {
            const int kk = ks * 16;
            uint32_t af[4][4];
            #pragma unroll
            for (int mi = 0; mi < 4; mi++) {
                const int r = wm * 64 + mi * 16 + gid;
                af[mi][0] = *(const uint32_t*)&As[buf][r * SST + kk + 2 * tig];
                af[mi][1] = *(const uint32_t*)&As[buf][(r + 8) * SST + kk + 2 * tig];
                af[mi][2] = *(const uint32_t*)&As[buf][r * SST + kk + 8 + 2 * tig];
                af[mi][3] = *(const uint32_t*)&As[buf][(r + 8) * SST + kk + 8 + 2 * tig];
            }
            uint32_t bfr[4][2];
            #pragma unroll
            for (int ni = 0; ni < 4; ni++) {
                const int c = wn * 32 + ni * 8 + gid;
                bfr[ni][0] = *(const uint32_t*)&Bs[buf][c * SST + kk + 2 * tig];
                bfr[ni][1] = *(const uint32_t*)&Bs[buf][c * SST + kk + 8 + 2 * tig];
            }
            #pragma unroll
            for (int mi = 0; mi < 4; mi++)
                #pragma unroll
                for (int ni = 0; ni < 4; ni++)
                    mma_bf16(acc[mi][ni], af[mi], bfr[ni]);
        }
        __syncthreads();
    }

    // Epilogue: relu(acc + qh) * v, reduced over this CTA's 128 d-columns.
    float pr[4][2];
    #pragma unroll
    for (int mi = 0; mi < 4; mi++) { pr[mi][0] = 0.f; pr[mi][1] = 0.f; }

    #pragma unroll
    for (int ni = 0; ni < 4; ni++) {
        const int c = n0 + wn * 32 + ni * 8 + tig * 2;
        const float q0 = g_qh[(size_t)bidx * DDIM + c];
        const float q1 = g_qh[(size_t)bidx * DDIM + c + 1];
        const float v0 = v[c];
        const float v1 = v[c + 1];
        #pragma unroll
        for (int mi = 0; mi < 4; mi++) {
            pr[mi][0] += fmaxf(acc[mi][ni][0] + q0, 0.f) * v0;
            pr[mi][0] += fmaxf(acc[mi][ni][1] + q1, 0.f) * v1;
            pr[mi][1] += fmaxf(acc[mi][ni][2] + q0, 0.f) * v0;
            pr[mi][1] += fmaxf(acc[mi][ni][3] + q1, 0.f) * v1;
        }
    }

    #pragma unroll
    for (int mi = 0; mi < 4; mi++)
        #pragma unroll
        for (int j = 0; j < 2; j++) {
            float p = pr[mi][j];
            p += __shfl_xor_sync(0xFFFFFFFFu, p, 1);
            p += __shfl_xor_sync(0xFFFFFFFFu, p, 2);
            if (tig == 0) partial[wn][wm * 64 + mi * 16 + j * 8 + gid] = p;
        }
    __syncthreads();

    if (tid < BM) {
        const float s = partial[0][tid] + partial[1][tid] + partial[2][tid] + partial[3][tid];
        g_part[(size_t)nx * MTOT + m0 + tid] = s;
    }
}

// ---------------------------------------------------------------------------
// Kernel: sum 8 N-strip partials -> scores, softmax over T.
__global__ __launch_bounds__(256) void softmax_kernel(float* __restrict__ out)
{
    const int b = blockIdx.x;
    const int tid = threadIdx.x;
    __shared__ float red[256];

    float vals[8];
    float mx = -1e30f;
    #pragma unroll
    for (int j = 0; j < 8; j++) {
        const int t = tid + j * 256;
        float s = 0.f;
        #pragma unroll
        for (int nxi = 0; nxi < NTILES; nxi++)
            s += g_part[(size_t)nxi * MTOT + (size_t)b * TDIM + t];
        vals[j] = s;
        mx = fmaxf(mx, s);
    }

    red[tid] = mx;
    __syncthreads();
    #pragma unroll
    for (int o = 128; o > 0; o >>= 1) {
        if (tid < o) red[tid] = fmaxf(red[tid], red[tid + o]);
        __syncthreads();
    }
    const float m = red[0];
    __syncthreads();

    float sum = 0.f;
    #pragma unroll
    for (int j = 0; j < 8; j++) {
        vals[j] = expf(vals[j] - m);
        sum += vals[j];
    }
    red[tid] = sum;
    __syncthreads();
    #pragma unroll
    for (int o = 128; o > 0; o >>= 1) {
        if (tid < o) red[tid] += red[tid + o];
        __syncthreads();
    }
    const float inv = 1.f / red[0];

    #pragma unroll
    for (int j = 0; j < 8; j++)
        out[(size_t)b * TDIM + tid + j * 256] = vals[j] * inv;
}

// ---------------------------------------------------------------------------
extern "C" void kernel_launch(void* const* d_in, const int* in_sizes, int n_in,
                              void* d_out, int out_size)
{
    const float* hidden = (const float*)d_in[0];
    const float* enc    = (const float*)d_in[1];
    const float* W      = (const float*)d_in[2];
    const float* bias   = (const float*)d_in[3];
    const float* v      = (const float*)d_in[4];
    float* out = (float*)d_out;

    conv_enc<<<65536, 256>>>((const float4*)enc);
    conv_w2<<<DDIM, 256>>>(W);
    qh_kernel<<<dim3(DDIM / 8, BDIM), 256>>>(hidden, W, bias);
    bf_gemm<<<dim3(NTILES, MTOT / BM), 256>>>(v);
    softmax_kernel<<<BDIM, 256>>>(out);
}